// round 14
// baseline (speedup 1.0000x reference)
#include <cuda_runtime.h>
#include <cuda_bf16.h>
#include <cstdint>

#define NMAX 200000
#define EMAX 400000
#define DD 128
#define HH 4
#define GDIM 148

typedef unsigned int uint;

// ---------------- scratch (device globals; no allocation) ----------------
__device__ __align__(16) uint  g_hh[NMAX*64];     // h hi-plane bf16 pairs
__device__ __align__(16) uint  g_hl[NMAX*64];     // h lo-plane bf16 pairs
__device__ __align__(16) float g_xl[NMAX*DD];
__device__ __align__(16) float g_xr[NMAX*DD];
__device__ __align__(16) float g_efull[(EMAX+NMAX)*HH];
__device__ __align__(16) float g_sums[NMAX*HH];
__device__ int g_deg[NMAX];
__device__ int g_off[NMAX+1];
__device__ int g_cur[NMAX];
__device__ int g_eid[EMAX+NMAX];
__device__ int g_bsum[260];

__device__ __forceinline__ void red4(float* p, float a, float b, float c, float d){
    asm volatile("red.global.add.v4.f32 [%0], {%1,%2,%3,%4};"
                 :: "l"(p), "f"(a), "f"(b), "f"(c), "f"(d) : "memory");
}

// split a pair of floats into bf16x2 (hi) + bf16x2 (lo residual)
__device__ __forceinline__ uint2 split2(float x0, float x1){
    __nv_bfloat162 h = __floats2bfloat162_rn(x0, x1);
    float r0 = x0 - __bfloat162float(h.x);
    float r1 = x1 - __bfloat162float(h.y);
    __nv_bfloat162 l = __floats2bfloat162_rn(r0, r1);
    uint2 u;
    u.x = *reinterpret_cast<uint32_t*>(&h);
    u.y = *reinterpret_cast<uint32_t*>(&l);
    return u;
}

// ---------------- atom encoder + split-plane store ----------------
__global__ void k_atom(const float* __restrict__ tab, const int* __restrict__ x, int n){
    int i = blockIdx.x;
    int d = threadIdx.x;        // 128 threads
    __shared__ int xf[9];
    if (d < 9) xf[d] = x[i*9 + d];
    __syncthreads();
    float s = 0.f;
#pragma unroll
    for (int f = 0; f < 9; ++f)
        s += tab[(f*16 + xf[f])*DD + d];
    float s1 = __shfl_down_sync(0xffffffffu, s, 1);
    if ((d & 1) == 0){
        uint2 u = split2(s, s1);
        g_hh[(size_t)i*64 + (d >> 1)] = u.x;
        g_hl[(size_t)i*64 + (d >> 1)] = u.y;
    }
}

__global__ void k_zero(int n){
    int i = blockIdx.x*blockDim.x + threadIdx.x;
    if (i >= n) return;
    g_deg[i] = 0;
    *(float4*)(g_sums + i*4) = make_float4(0.f,0.f,0.f,0.f);
}

__global__ void k_edge(const float* __restrict__ bond, const int* __restrict__ ei,
                       const int* __restrict__ ea, int E_){
    int e = blockIdx.x*blockDim.x + threadIdx.x;
    if (e >= E_) return;
    int tt  = ea[e];
    int dst = ei[E_ + e];
    float4 b = *(const float4*)(bond + tt*4);
    *(float4*)(g_efull + e*4) = b;
    red4(g_sums + dst*4, b.x, b.y, b.z, b.w);
    atomicAdd(g_deg + dst, 1);
}

__global__ void k_self(int E_, int n){
    int i = blockIdx.x*blockDim.x + threadIdx.x;
    if (i >= n) return;
    float inv = 1.0f / fmaxf((float)g_deg[i], 1.0f);
    float4 s = *(const float4*)(g_sums + i*4);
    *(float4*)(g_efull + (E_ + i)*4) = make_float4(s.x*inv, s.y*inv, s.z*inv, s.w*inv);
}

// ---------------- CSR build ----------------
__global__ void k_scan1(int n){
    __shared__ int ws[8];
    int t = threadIdx.x, b = blockIdx.x;
    int base = b*1024 + t*4;
    int v[4];
#pragma unroll
    for (int j = 0; j < 4; ++j){
        int i = base + j;
        v[j] = (i < n) ? (g_deg[i] + 1) : 0;
    }
    int s = v[0] + v[1] + v[2] + v[3];
    int lane = t & 31, wid = t >> 5;
    int x = s;
#pragma unroll
    for (int o = 1; o < 32; o <<= 1){
        int y = __shfl_up_sync(0xffffffffu, x, o);
        if (lane >= o) x += y;
    }
    if (lane == 31) ws[wid] = x;
    __syncthreads();
    if (t == 0){
        int r = 0;
#pragma unroll
        for (int w = 0; w < 8; ++w){ int tmp = ws[w]; ws[w] = r; r += tmp; }
        g_bsum[b] = r;
    }
    __syncthreads();
    int run = x - s + ws[wid];
#pragma unroll
    for (int j = 0; j < 4; ++j){
        int i = base + j;
        if (i < n) g_off[i] = run;
        run += v[j];
    }
}

__global__ void k_scan2(int nb){
    int r = 0;
    for (int b = 0; b < nb; ++b){ int t = g_bsum[b]; g_bsum[b] = r; r += t; }
    g_bsum[nb] = r;
}

__global__ void k_scan3(int n, int nb){
    int i = blockIdx.x*blockDim.x + threadIdx.x;
    if (i == 0) g_off[n] = g_bsum[nb];
    if (i >= n) return;
    int o = g_off[i] + g_bsum[i >> 10];
    g_off[i] = o;
    g_cur[i] = o;
}

__global__ void k_scatter(const int* __restrict__ ei, int E_, int n){
    int e = blockIdx.x*blockDim.x + threadIdx.x;
    if (e >= E_ + n) return;
    int dst = (e < E_) ? ei[E_ + e] : (e - E_);
    int pos = atomicAdd(g_cur + dst, 1);
    g_eid[pos] = e;
}

// ---------------- bf16-split dual GEMM via ldmatrix (R9 exact) ----------------
#define RSU 68   // uints per row (272 B)
#define MMA1(acc, a0,a1,a2,a3, b0,b1) \
    asm volatile("mma.sync.aligned.m16n8k16.row.col.f32.bf16.bf16.f32 " \
        "{%0,%1,%2,%3}, {%4,%5,%6,%7}, {%8,%9}, {%0,%1,%2,%3};" \
        : "+f"(acc[0]), "+f"(acc[1]), "+f"(acc[2]), "+f"(acc[3]) \
        : "r"(a0), "r"(a1), "r"(a2), "r"(a3), "r"(b0), "r"(b1))
#define LDSM4(f, addr) \
    asm volatile("ldmatrix.sync.aligned.m8n8.x4.shared.b16 {%0,%1,%2,%3}, [%4];" \
        : "=r"(f[0]), "=r"(f[1]), "=r"(f[2]), "=r"(f[3]) : "r"(addr))

__global__ __launch_bounds__(256, 1)
void k_tc(const float* __restrict__ Wl, const float* __restrict__ bl,
          const float* __restrict__ Wr, const float* __restrict__ br, int n){
    extern __shared__ uint smu[];
    uint* sBh = smu;                   // [256][RSU]
    uint* sBl = sBh + 256*RSU;
    uint* sAh = sBl + 256*RSU;         // [64][RSU]
    uint* sAl = sAh + 64*RSU;
    float* sBias = (float*)(sAl + 64*RSU);   // [256]
    int tid = threadIdx.x, wid = tid >> 5, lane = tid & 31;
    int gq = lane >> 2, tg = lane & 3;
    int wm = wid & 1, wn = wid >> 1;

    for (int idx = tid; idx < 256*64; idx += 256){
        int c = idx & 255, kp = idx >> 8;
        int k = kp*2;
        float w0, w1;
        if (c < 128){ w0 = Wl[k*DD + c];        w1 = Wl[(k+1)*DD + c]; }
        else        { w0 = Wr[k*DD + (c-128)];  w1 = Wr[(k+1)*DD + (c-128)]; }
        uint2 u = split2(w0, w1);
        sBh[c*RSU + kp] = u.x;
        sBl[c*RSU + kp] = u.y;
    }
    sBias[tid] = (tid < 128) ? bl[tid] : br[tid - 128];

    uint32_t sA_h32, sA_l32, sB_h32, sB_l32;
    asm("{ .reg .u64 t; cvta.to.shared.u64 t, %1; cvt.u32.u64 %0, t; }" : "=r"(sA_h32) : "l"(sAh));
    asm("{ .reg .u64 t; cvta.to.shared.u64 t, %1; cvt.u32.u64 %0, t; }" : "=r"(sA_l32) : "l"(sAl));
    asm("{ .reg .u64 t; cvta.to.shared.u64 t, %1; cvt.u32.u64 %0, t; }" : "=r"(sB_h32) : "l"(sBh));
    asm("{ .reg .u64 t; cvta.to.shared.u64 t, %1; cvt.u32.u64 %0, t; }" : "=r"(sB_l32) : "l"(sBl));

    int tiles = (n + 63) >> 6;
    uint4 preH[4], preL[4];
    {
        int base = blockIdx.x * 64;
#pragma unroll
        for (int r = 0; r < 4; ++r){
            int cidx = r*256 + tid;
            int node = cidx >> 4, ch = cidx & 15;
            int gn = base + node;
            if (gn < n){
                preH[r] = ((const uint4*)(g_hh + (size_t)gn*64))[ch];
                preL[r] = ((const uint4*)(g_hl + (size_t)gn*64))[ch];
            } else {
                preH[r] = make_uint4(0u,0u,0u,0u);
                preL[r] = make_uint4(0u,0u,0u,0u);
            }
        }
    }

    for (int tile = blockIdx.x; tile < tiles; tile += GDIM){
        __syncthreads();
#pragma unroll
        for (int r = 0; r < 4; ++r){
            int cidx = r*256 + tid;
            int node = cidx >> 4, ch = cidx & 15;
            *(uint4*)(sAh + node*RSU + ch*4) = preH[r];
            *(uint4*)(sAl + node*RSU + ch*4) = preL[r];
        }
        __syncthreads();
        if (tile + GDIM < tiles){
            int base = (tile + GDIM) * 64;
#pragma unroll
            for (int r = 0; r < 4; ++r){
                int cidx = r*256 + tid;
                int node = cidx >> 4, ch = cidx & 15;
                int gn = base + node;
                if (gn < n){
                    preH[r] = ((const uint4*)(g_hh + (size_t)gn*64))[ch];
                    preL[r] = ((const uint4*)(g_hl + (size_t)gn*64))[ch];
                } else {
                    preH[r] = make_uint4(0u,0u,0u,0u);
                    preL[r] = make_uint4(0u,0u,0u,0u);
                }
            }
        }

        float acc[2][8][4];
#pragma unroll
        for (int mb = 0; mb < 2; ++mb)
#pragma unroll
            for (int nb = 0; nb < 8; ++nb)
#pragma unroll
                for (int j = 0; j < 4; ++j) acc[mb][nb][j] = 0.f;

        uint32_t l15 = (uint32_t)(lane & 15);
        uint32_t lhi = (uint32_t)(lane >> 4) * 16u;

#pragma unroll 1
        for (int kc = 0; kc < 8; ++kc){
            uint32_t koff = (uint32_t)kc*32u + lhi;
            uint32_t ah[2][4], al[2][4], bh[4][4], blo[4][4];
#pragma unroll
            for (int mb = 0; mb < 2; ++mb){
                uint32_t ro = (uint32_t)(wm*32 + mb*16) + l15;
                LDSM4(ah[mb], sA_h32 + ro*272u + koff);
                LDSM4(al[mb], sA_l32 + ro*272u + koff);
            }
#pragma unroll
            for (int cb = 0; cb < 4; ++cb){
                uint32_t co = (uint32_t)(wn*64 + cb*16) + l15;
                LDSM4(bh[cb],  sB_h32 + co*272u + koff);
                LDSM4(blo[cb], sB_l32 + co*272u + koff);
            }
#pragma unroll
            for (int nb = 0; nb < 8; ++nb){
                int cb = nb >> 1, hf = nb & 1;
                uint32_t bh0 = bh[cb][hf],  bh1 = bh[cb][hf+2];
                uint32_t bl0 = blo[cb][hf], bl1 = blo[cb][hf+2];
#pragma unroll
                for (int mb = 0; mb < 2; ++mb){
                    MMA1(acc[mb][nb], ah[mb][0],ah[mb][1],ah[mb][2],ah[mb][3], bh0,bh1);
                    MMA1(acc[mb][nb], ah[mb][0],ah[mb][1],ah[mb][2],ah[mb][3], bl0,bl1);
                    MMA1(acc[mb][nb], al[mb][0],al[mb][1],al[mb][2],al[mb][3], bh0,bh1);
                }
            }
        }

        int base = tile*64;
#pragma unroll
        for (int mb = 0; mb < 2; ++mb){
            int gm0 = base + wm*32 + mb*16 + gq;
            int gm1 = gm0 + 8;
#pragma unroll
            for (int nb = 0; nb < 8; ++nb){
                int c0 = wn*64 + nb*8 + tg*2;
                float bx = sBias[c0], by = sBias[c0 + 1];
                float* outp = (c0 < 128) ? g_xl : g_xr;
                int cl = (c0 < 128) ? c0 : c0 - 128;
                if (gm0 < n)
                    *(float2*)(outp + (size_t)gm0*DD + cl)
                        = make_float2(acc[mb][nb][0] + bx, acc[mb][nb][1] + by);
                if (gm1 < n)
                    *(float2*)(outp + (size_t)gm1*DD + cl)
                        = make_float2(acc[mb][nb][2] + bx, acc[mb][nb][3] + by);
            }
        }
    }
}

// ---------------- CSR fused edge pass, depth-2 gather pipeline ----------------
// Warp per dst node (R9 coalesced pattern). Edge jj+1's e4/a4 gathers are
// issued before edge jj's compute, overlapping gather latency with the
// logit/expf chain. Last layer fuses the output head (h . Wout -> out[bid]).
__global__ void k_att2(const int* __restrict__ ei, const float* __restrict__ We,
                       const float* __restrict__ att, const float* __restrict__ cb,
                       const float* __restrict__ Wout, const int* __restrict__ bid,
                       float* __restrict__ out, int E_, int n, int last){
    __shared__ float sWe[4*DD];
    __shared__ float sAtt[DD];
    __shared__ float sCb[DD];
    int t = threadIdx.x;
    for (int i = t; i < 4*DD; i += 256) sWe[i] = We[i];
    if (t < DD){ sAtt[t] = att[t]; sCb[t] = cb[t]; }
    __syncthreads();

    int d = blockIdx.x*8 + (t >> 5);
    if (d >= n) return;
    int lane = t & 31;
    int off0 = g_off[d], off1 = g_off[d+1];
    int c0 = lane*4;

    float4 b4 = *(const float4*)(g_xr + (size_t)d*DD + c0);
    float acc0 = 0.f, acc1 = 0.f, acc2 = 0.f, acc3 = 0.f;
    float zacc = 0.f;

    for (int jb = off0; jb < off1; jb += 32){
        int m = min(32, off1 - jb);
        int idx = 0, src = d;
        if (lane < m){
            idx = g_eid[jb + lane];
            src = (idx < E_) ? ei[idx] : d;
        }
        // prefetch edge 0
        int e0  = __shfl_sync(0xffffffffu, idx, 0);
        int s0  = __shfl_sync(0xffffffffu, src, 0);
        float4 e4n = *(const float4*)(g_efull + (size_t)e0*4);
        float4 a4n = *(const float4*)(g_xl + (size_t)s0*DD + c0);
#pragma unroll 1
        for (int jj = 0; jj < m; ++jj){
            float4 e4 = e4n;
            float4 a4 = a4n;
            if (jj + 1 < m){
                int e1 = __shfl_sync(0xffffffffu, idx, jj + 1);
                int s1 = __shfl_sync(0xffffffffu, src, jj + 1);
                e4n = *(const float4*)(g_efull + (size_t)e1*4);
                a4n = *(const float4*)(g_xl + (size_t)s1*DD + c0);
            }
            float av[4] = {a4.x, a4.y, a4.z, a4.w};
            float bv[4] = {b4.x, b4.y, b4.z, b4.w};
            float p = 0.f;
#pragma unroll
            for (int j = 0; j < 4; ++j){
                int c = c0 + j;
                float ee = e4.x*sWe[c] + e4.y*sWe[DD + c]
                         + e4.z*sWe[2*DD + c] + e4.w*sWe[3*DD + c];
                float g = av[j] + bv[j] + ee;
                g = (g > 0.f) ? g : 0.2f*g;
                p += g * sAtt[c];
            }
            p += __shfl_xor_sync(0xffffffffu, p, 1);
            p += __shfl_xor_sync(0xffffffffu, p, 2);
            p += __shfl_xor_sync(0xffffffffu, p, 4);
            float w = 0.f;
            if ((lane & 7) == 0){
                w = expf(p);
                zacc += w;
            }
            w = __shfl_sync(0xffffffffu, w, lane & 24);
            acc0 += av[0]*w; acc1 += av[1]*w; acc2 += av[2]*w; acc3 += av[3]*w;
        }
    }

    float z = __shfl_sync(0xffffffffu, zacc, lane & 24);
    float inv = 1.0f / (z + 1e-16f);
    float4 o;
    o.x = acc0*inv + sCb[c0];
    o.y = acc1*inv + sCb[c0+1];
    o.z = acc2*inv + sCb[c0+2];
    o.w = acc3*inv + sCb[c0+3];

    if (last){
        // fused head: out[bid[d]] += h[d] . Wout
        float4 wv = *(const float4*)(Wout + c0);
        float p = o.x*wv.x + o.y*wv.y + o.z*wv.z + o.w*wv.w;
#pragma unroll
        for (int off = 16; off > 0; off >>= 1)
            p += __shfl_xor_sync(0xffffffffu, p, off);
        if (lane == 0) atomicAdd(out + bid[d], p);
        return;
    }
    o.x = fmaxf(o.x, 0.f); o.y = fmaxf(o.y, 0.f);
    o.z = fmaxf(o.z, 0.f); o.w = fmaxf(o.w, 0.f);
    uint2 u0 = split2(o.x, o.y);
    uint2 u1 = split2(o.z, o.w);
    *(uint2*)(g_hh + (size_t)d*64 + lane*2) = make_uint2(u0.x, u1.x);
    *(uint2*)(g_hl + (size_t)d*64 + lane*2) = make_uint2(u0.y, u1.y);
}

// ---------------- head init ----------------
__global__ void k_head(float* out, const float* __restrict__ bout, int G){
    int g = blockIdx.x*blockDim.x + threadIdx.x;
    if (g < G) out[g] = bout[0];
}

// ---------------- launch ----------------
extern "C" void kernel_launch(void* const* d_in, const int* in_sizes, int n_in,
                              void* d_out, int out_size){
    const float* atab = (const float*)d_in[0];
    const float* bond = (const float*)d_in[1];
    const float* Wl   = (const float*)d_in[2];
    const float* bl   = (const float*)d_in[3];
    const float* Wr   = (const float*)d_in[4];
    const float* br   = (const float*)d_in[5];
    const float* We   = (const float*)d_in[6];
    const float* att  = (const float*)d_in[7];
    const float* cb   = (const float*)d_in[8];
    const float* Wout = (const float*)d_in[9];
    const float* bout = (const float*)d_in[10];
    const int*   x    = (const int*)d_in[11];
    const int*   ei   = (const int*)d_in[12];
    const int*   ea   = (const int*)d_in[13];
    const int*   bid  = (const int*)d_in[14];

    int n  = in_sizes[11] / 9;
    int E_ = in_sizes[13];
    int G  = out_size;
    float* out = (float*)d_out;

    const int SMEM = (256*RSU*2 + 64*RSU*2)*4 + 256*4;   // ~171 KB
    cudaFuncSetAttribute(k_tc, cudaFuncAttributeMaxDynamicSharedMemorySize, SMEM);

    int nb = (n + 255)/256;
    int nsb = (n + 1023)/1024;
    int M  = E_ + n;

    k_atom<<<n, 128>>>(atab, x, n);
    k_zero<<<nb, 256>>>(n);
    k_edge<<<(E_ + 255)/256, 256>>>(bond, ei, ea, E_);
    k_tc<<<GDIM, 256, SMEM>>>(Wl, bl, Wr, br, n);      // layer-0 GEMM (ncu window)
    k_self<<<nb, 256>>>(E_, n);
    k_scan1<<<nsb, 256>>>(n);
    k_scan2<<<1, 1>>>(nsb);
    k_scan3<<<nb, 256>>>(n, nsb);
    k_scatter<<<(M + 255)/256, 256>>>(ei, E_, n);
    k_head<<<(G + 255)/256, 256>>>(out, bout, G);
    k_att2<<<(n + 7)/8, 256>>>(ei, We, att, cb, Wout, bid, out, E_, n, 0);

    for (int l = 1; l < 4; ++l){
        k_tc<<<GDIM, 256, SMEM>>>(Wl + l*DD*DD, bl + l*DD, Wr + l*DD*DD, br + l*DD, n);
        k_att2<<<(n + 7)/8, 256>>>(ei, We + l*4*DD, att + l*DD, cb + l*DD,
                                   Wout, bid, out, E_, n, (l == 3) ? 1 : 0);
    }
}

// round 15
// speedup vs baseline: 1.0173x; 1.0173x over previous
#include <cuda_runtime.h>
#include <cuda_bf16.h>
#include <cstdint>

#define NMAX 200000
#define EMAX 400000
#define DD 128
#define HH 4
#define GDIM 148

typedef unsigned int uint;

// ---------------- scratch (device globals; no allocation) ----------------
__device__ __align__(16) float g_h[NMAX*DD];      // final-layer h (for pool)
__device__ __align__(16) uint  g_hh[NMAX*64];     // h hi-plane bf16 pairs
__device__ __align__(16) uint  g_hl[NMAX*64];     // h lo-plane bf16 pairs
__device__ __align__(16) float g_xl[NMAX*DD];
__device__ __align__(16) float g_xr[NMAX*DD];
__device__ __align__(16) float g_efull[(EMAX+NMAX)*HH];
__device__ __align__(16) float g_sums[NMAX*HH];
__device__ int g_deg[NMAX];
__device__ int g_off[NMAX];
__device__ int g_cur[NMAX];
__device__ int g_eid[EMAX+NMAX];
__device__ int g_total;

__device__ __forceinline__ void red4(float* p, float a, float b, float c, float d){
    asm volatile("red.global.add.v4.f32 [%0], {%1,%2,%3,%4};"
                 :: "l"(p), "f"(a), "f"(b), "f"(c), "f"(d) : "memory");
}

// split a pair of floats into bf16x2 (hi) + bf16x2 (lo residual)
__device__ __forceinline__ uint2 split2(float x0, float x1){
    __nv_bfloat162 h = __floats2bfloat162_rn(x0, x1);
    float r0 = x0 - __bfloat162float(h.x);
    float r1 = x1 - __bfloat162float(h.y);
    __nv_bfloat162 l = __floats2bfloat162_rn(r0, r1);
    uint2 u;
    u.x = *reinterpret_cast<uint32_t*>(&h);
    u.y = *reinterpret_cast<uint32_t*>(&l);
    return u;
}

// ---------------- atom encoder + split-plane store ----------------
__global__ void k_atom(const float* __restrict__ tab, const int* __restrict__ x, int n){
    int i = blockIdx.x;
    int d = threadIdx.x;        // 128 threads
    __shared__ int xf[9];
    if (d < 9) xf[d] = x[i*9 + d];
    __syncthreads();
    float s = 0.f;
#pragma unroll
    for (int f = 0; f < 9; ++f)
        s += tab[(f*16 + xf[f])*DD + d];
    float s1 = __shfl_down_sync(0xffffffffu, s, 1);
    if ((d & 1) == 0){
        uint2 u = split2(s, s1);
        g_hh[(size_t)i*64 + (d >> 1)] = u.x;
        g_hl[(size_t)i*64 + (d >> 1)] = u.y;
    }
}

__global__ void k_zero(int n){
    int i = blockIdx.x*blockDim.x + threadIdx.x;
    if (i == 0) g_total = 0;
    if (i >= n) return;
    g_deg[i] = 0;
    *(float4*)(g_sums + i*4) = make_float4(0.f,0.f,0.f,0.f);
}

__global__ void k_edge(const float* __restrict__ bond, const int* __restrict__ ei,
                       const int* __restrict__ ea, int E_){
    int e = blockIdx.x*blockDim.x + threadIdx.x;
    if (e >= E_) return;
    int tt  = ea[e];
    int dst = ei[E_ + e];
    float4 b = *(const float4*)(bond + tt*4);
    *(float4*)(g_efull + e*4) = b;
    red4(g_sums + dst*4, b.x, b.y, b.z, b.w);
    atomicAdd(g_deg + dst, 1);
}

// self-loop mean + atomic CSR offset assignment (order-free segments)
__global__ void k_self(int E_, int n){
    int i = blockIdx.x*blockDim.x + threadIdx.x;
    if (i >= n) return;
    int deg = g_deg[i];
    float inv = 1.0f / fmaxf((float)deg, 1.0f);
    float4 s = *(const float4*)(g_sums + i*4);
    *(float4*)(g_efull + (E_ + i)*4) = make_float4(s.x*inv, s.y*inv, s.z*inv, s.w*inv);
    int pos = atomicAdd(&g_total, deg + 1);
    g_off[i] = pos;
    g_cur[i] = pos;
}

__global__ void k_scatter(const int* __restrict__ ei, int E_, int n){
    int e = blockIdx.x*blockDim.x + threadIdx.x;
    if (e >= E_ + n) return;
    int dst = (e < E_) ? ei[E_ + e] : (e - E_);
    int pos = atomicAdd(g_cur + dst, 1);
    g_eid[pos] = e;
}

// ---------------- bf16-split dual GEMM via ldmatrix (R9 exact) ----------------
#define RSU 68   // uints per row (272 B)
#define MMA1(acc, a0,a1,a2,a3, b0,b1) \
    asm volatile("mma.sync.aligned.m16n8k16.row.col.f32.bf16.bf16.f32 " \
        "{%0,%1,%2,%3}, {%4,%5,%6,%7}, {%8,%9}, {%0,%1,%2,%3};" \
        : "+f"(acc[0]), "+f"(acc[1]), "+f"(acc[2]), "+f"(acc[3]) \
        : "r"(a0), "r"(a1), "r"(a2), "r"(a3), "r"(b0), "r"(b1))
#define LDSM4(f, addr) \
    asm volatile("ldmatrix.sync.aligned.m8n8.x4.shared.b16 {%0,%1,%2,%3}, [%4];" \
        : "=r"(f[0]), "=r"(f[1]), "=r"(f[2]), "=r"(f[3]) : "r"(addr))

__global__ __launch_bounds__(256, 1)
void k_tc(const float* __restrict__ Wl, const float* __restrict__ bl,
          const float* __restrict__ Wr, const float* __restrict__ br, int n){
    extern __shared__ uint smu[];
    uint* sBh = smu;                   // [256][RSU]
    uint* sBl = sBh + 256*RSU;
    uint* sAh = sBl + 256*RSU;         // [64][RSU]
    uint* sAl = sAh + 64*RSU;
    float* sBias = (float*)(sAl + 64*RSU);   // [256]
    int tid = threadIdx.x, wid = tid >> 5, lane = tid & 31;
    int gq = lane >> 2, tg = lane & 3;
    int wm = wid & 1, wn = wid >> 1;

    for (int idx = tid; idx < 256*64; idx += 256){
        int c = idx & 255, kp = idx >> 8;
        int k = kp*2;
        float w0, w1;
        if (c < 128){ w0 = Wl[k*DD + c];        w1 = Wl[(k+1)*DD + c]; }
        else        { w0 = Wr[k*DD + (c-128)];  w1 = Wr[(k+1)*DD + (c-128)]; }
        uint2 u = split2(w0, w1);
        sBh[c*RSU + kp] = u.x;
        sBl[c*RSU + kp] = u.y;
    }
    sBias[tid] = (tid < 128) ? bl[tid] : br[tid - 128];

    uint32_t sA_h32, sA_l32, sB_h32, sB_l32;
    asm("{ .reg .u64 t; cvta.to.shared.u64 t, %1; cvt.u32.u64 %0, t; }" : "=r"(sA_h32) : "l"(sAh));
    asm("{ .reg .u64 t; cvta.to.shared.u64 t, %1; cvt.u32.u64 %0, t; }" : "=r"(sA_l32) : "l"(sAl));
    asm("{ .reg .u64 t; cvta.to.shared.u64 t, %1; cvt.u32.u64 %0, t; }" : "=r"(sB_h32) : "l"(sBh));
    asm("{ .reg .u64 t; cvta.to.shared.u64 t, %1; cvt.u32.u64 %0, t; }" : "=r"(sB_l32) : "l"(sBl));

    int tiles = (n + 63) >> 6;
    uint4 preH[4], preL[4];
    {
        int base = blockIdx.x * 64;
#pragma unroll
        for (int r = 0; r < 4; ++r){
            int cidx = r*256 + tid;
            int node = cidx >> 4, ch = cidx & 15;
            int gn = base + node;
            if (gn < n){
                preH[r] = ((const uint4*)(g_hh + (size_t)gn*64))[ch];
                preL[r] = ((const uint4*)(g_hl + (size_t)gn*64))[ch];
            } else {
                preH[r] = make_uint4(0u,0u,0u,0u);
                preL[r] = make_uint4(0u,0u,0u,0u);
            }
        }
    }

    for (int tile = blockIdx.x; tile < tiles; tile += GDIM){
        __syncthreads();
#pragma unroll
        for (int r = 0; r < 4; ++r){
            int cidx = r*256 + tid;
            int node = cidx >> 4, ch = cidx & 15;
            *(uint4*)(sAh + node*RSU + ch*4) = preH[r];
            *(uint4*)(sAl + node*RSU + ch*4) = preL[r];
        }
        __syncthreads();
        if (tile + GDIM < tiles){
            int base = (tile + GDIM) * 64;
#pragma unroll
            for (int r = 0; r < 4; ++r){
                int cidx = r*256 + tid;
                int node = cidx >> 4, ch = cidx & 15;
                int gn = base + node;
                if (gn < n){
                    preH[r] = ((const uint4*)(g_hh + (size_t)gn*64))[ch];
                    preL[r] = ((const uint4*)(g_hl + (size_t)gn*64))[ch];
                } else {
                    preH[r] = make_uint4(0u,0u,0u,0u);
                    preL[r] = make_uint4(0u,0u,0u,0u);
                }
            }
        }

        float acc[2][8][4];
#pragma unroll
        for (int mb = 0; mb < 2; ++mb)
#pragma unroll
            for (int nb = 0; nb < 8; ++nb)
#pragma unroll
                for (int j = 0; j < 4; ++j) acc[mb][nb][j] = 0.f;

        uint32_t l15 = (uint32_t)(lane & 15);
        uint32_t lhi = (uint32_t)(lane >> 4) * 16u;

#pragma unroll 1
        for (int kc = 0; kc < 8; ++kc){
            uint32_t koff = (uint32_t)kc*32u + lhi;
            uint32_t ah[2][4], al[2][4], bh[4][4], blo[4][4];
#pragma unroll
            for (int mb = 0; mb < 2; ++mb){
                uint32_t ro = (uint32_t)(wm*32 + mb*16) + l15;
                LDSM4(ah[mb], sA_h32 + ro*272u + koff);
                LDSM4(al[mb], sA_l32 + ro*272u + koff);
            }
#pragma unroll
            for (int cb = 0; cb < 4; ++cb){
                uint32_t co = (uint32_t)(wn*64 + cb*16) + l15;
                LDSM4(bh[cb],  sB_h32 + co*272u + koff);
                LDSM4(blo[cb], sB_l32 + co*272u + koff);
            }
#pragma unroll
            for (int nb = 0; nb < 8; ++nb){
                int cb = nb >> 1, hf = nb & 1;
                uint32_t bh0 = bh[cb][hf],  bh1 = bh[cb][hf+2];
                uint32_t bl0 = blo[cb][hf], bl1 = blo[cb][hf+2];
#pragma unroll
                for (int mb = 0; mb < 2; ++mb){
                    MMA1(acc[mb][nb], ah[mb][0],ah[mb][1],ah[mb][2],ah[mb][3], bh0,bh1);
                    MMA1(acc[mb][nb], ah[mb][0],ah[mb][1],ah[mb][2],ah[mb][3], bl0,bl1);
                    MMA1(acc[mb][nb], al[mb][0],al[mb][1],al[mb][2],al[mb][3], bh0,bh1);
                }
            }
        }

        int base = tile*64;
#pragma unroll
        for (int mb = 0; mb < 2; ++mb){
            int gm0 = base + wm*32 + mb*16 + gq;
            int gm1 = gm0 + 8;
#pragma unroll
            for (int nb = 0; nb < 8; ++nb){
                int c0 = wn*64 + nb*8 + tg*2;
                float bx = sBias[c0], by = sBias[c0 + 1];
                float* outp = (c0 < 128) ? g_xl : g_xr;
                int cl = (c0 < 128) ? c0 : c0 - 128;
                if (gm0 < n)
                    *(float2*)(outp + (size_t)gm0*DD + cl)
                        = make_float2(acc[mb][nb][0] + bx, acc[mb][nb][1] + by);
                if (gm1 < n)
                    *(float2*)(outp + (size_t)gm1*DD + cl)
                        = make_float2(acc[mb][nb][2] + bx, acc[mb][nb][3] + by);
            }
        }
    }
}

// ---------------- CSR fused edge pass (R9 exact; off1 from deg) ----------------
__global__ void k_att2(const int* __restrict__ ei, const float* __restrict__ We,
                       const float* __restrict__ att, const float* __restrict__ cb,
                       int E_, int n, int last){
    __shared__ float sWe[4*DD];
    __shared__ float sAtt[DD];
    __shared__ float sCb[DD];
    int t = threadIdx.x;
    for (int i = t; i < 4*DD; i += 256) sWe[i] = We[i];
    if (t < DD){ sAtt[t] = att[t]; sCb[t] = cb[t]; }
    __syncthreads();

    int d = blockIdx.x*8 + (t >> 5);
    if (d >= n) return;
    int lane = t & 31;
    int off0 = g_off[d];
    int off1 = off0 + g_deg[d] + 1;
    int c0 = lane*4;

    float4 b4 = *(const float4*)(g_xr + (size_t)d*DD + c0);
    float acc0 = 0.f, acc1 = 0.f, acc2 = 0.f, acc3 = 0.f;
    float zacc = 0.f;

    for (int jb = off0; jb < off1; jb += 32){
        int m = min(32, off1 - jb);
        int idx = 0, src = d;
        if (lane < m){
            idx = g_eid[jb + lane];
            src = (idx < E_) ? ei[idx] : d;
        }
#pragma unroll 1
        for (int jj = 0; jj < m; ++jj){
            int eidx = __shfl_sync(0xffffffffu, idx, jj);
            int esrc = __shfl_sync(0xffffffffu, src, jj);
            float4 e4 = *(const float4*)(g_efull + (size_t)eidx*4);
            float4 a4 = *(const float4*)(g_xl + (size_t)esrc*DD + c0);
            float av[4] = {a4.x, a4.y, a4.z, a4.w};
            float bv[4] = {b4.x, b4.y, b4.z, b4.w};
            float p = 0.f;
#pragma unroll
            for (int j = 0; j < 4; ++j){
                int c = c0 + j;
                float ee = e4.x*sWe[c] + e4.y*sWe[DD + c]
                         + e4.z*sWe[2*DD + c] + e4.w*sWe[3*DD + c];
                float g = av[j] + bv[j] + ee;
                g = (g > 0.f) ? g : 0.2f*g;
                p += g * sAtt[c];
            }
            p += __shfl_xor_sync(0xffffffffu, p, 1);
            p += __shfl_xor_sync(0xffffffffu, p, 2);
            p += __shfl_xor_sync(0xffffffffu, p, 4);
            float w = 0.f;
            if ((lane & 7) == 0){
                w = expf(p);
                zacc += w;
            }
            w = __shfl_sync(0xffffffffu, w, lane & 24);
            acc0 += av[0]*w; acc1 += av[1]*w; acc2 += av[2]*w; acc3 += av[3]*w;
        }
    }

    float z = __shfl_sync(0xffffffffu, zacc, lane & 24);
    float inv = 1.0f / (z + 1e-16f);
    float4 o;
    o.x = acc0*inv + sCb[c0];
    o.y = acc1*inv + sCb[c0+1];
    o.z = acc2*inv + sCb[c0+2];
    o.w = acc3*inv + sCb[c0+3];

    if (last){
        *(float4*)(g_h + (size_t)d*DD + c0) = o;
        return;
    }
    o.x = fmaxf(o.x, 0.f); o.y = fmaxf(o.y, 0.f);
    o.z = fmaxf(o.z, 0.f); o.w = fmaxf(o.w, 0.f);
    uint2 u0 = split2(o.x, o.y);
    uint2 u1 = split2(o.z, o.w);
    *(uint2*)(g_hh + (size_t)d*64 + lane*2) = make_uint2(u0.x, u1.x);
    *(uint2*)(g_hl + (size_t)d*64 + lane*2) = make_uint2(u0.y, u1.y);
}

// ---------------- head ----------------
__global__ void k_head(float* out, const float* __restrict__ bout, int G){
    int g = blockIdx.x*blockDim.x + threadIdx.x;
    if (g < G) out[g] = bout[0];
}

__global__ void k_pool(const float* __restrict__ Wout, const int* __restrict__ bid,
                       float* out, int n){
    int gw   = blockIdx.x*8 + (threadIdx.x >> 5);
    int lane = threadIdx.x & 31;
    if (gw >= n) return;
    float4 hv = *(const float4*)(g_h + (size_t)gw*DD + lane*4);
    float4 wv = *(const float4*)(Wout + lane*4);
    float p = hv.x*wv.x + hv.y*wv.y + hv.z*wv.z + hv.w*wv.w;
#pragma unroll
    for (int o = 16; o > 0; o >>= 1) p += __shfl_xor_sync(0xffffffffu, p, o);
    if (lane == 0) atomicAdd(out + bid[gw], p);
}

// ---------------- launch ----------------
extern "C" void kernel_launch(void* const* d_in, const int* in_sizes, int n_in,
                              void* d_out, int out_size){
    const float* atab = (const float*)d_in[0];
    const float* bond = (const float*)d_in[1];
    const float* Wl   = (const float*)d_in[2];
    const float* bl   = (const float*)d_in[3];
    const float* Wr   = (const float*)d_in[4];
    const float* br   = (const float*)d_in[5];
    const float* We   = (const float*)d_in[6];
    const float* att  = (const float*)d_in[7];
    const float* cb   = (const float*)d_in[8];
    const float* Wout = (const float*)d_in[9];
    const float* bout = (const float*)d_in[10];
    const int*   x    = (const int*)d_in[11];
    const int*   ei   = (const int*)d_in[12];
    const int*   ea   = (const int*)d_in[13];
    const int*   bid  = (const int*)d_in[14];

    int n  = in_sizes[11] / 9;
    int E_ = in_sizes[13];
    int G  = out_size;
    float* out = (float*)d_out;

    const int SMEM = (256*RSU*2 + 64*RSU*2)*4 + 256*4;   // ~171 KB
    cudaFuncSetAttribute(k_tc, cudaFuncAttributeMaxDynamicSharedMemorySize, SMEM);

    int nb = (n + 255)/256;
    int M  = E_ + n;

    k_atom<<<n, 128>>>(atab, x, n);
    k_zero<<<nb, 256>>>(n);
    k_edge<<<(E_ + 255)/256, 256>>>(bond, ei, ea, E_);
    k_tc<<<GDIM, 256, SMEM>>>(Wl, bl, Wr, br, n);      // layer-0 GEMM (ncu window)
    k_self<<<nb, 256>>>(E_, n);
    k_scatter<<<(M + 255)/256, 256>>>(ei, E_, n);
    k_att2<<<(n + 7)/8, 256>>>(ei, We, att, cb, E_, n, 0);

    for (int l = 1; l < 4; ++l){
        k_tc<<<GDIM, 256, SMEM>>>(Wl + l*DD*DD, bl + l*DD, Wr + l*DD*DD, br + l*DD, n);
        k_att2<<<(n + 7)/8, 256>>>(ei, We + l*4*DD, att + l*DD, cb + l*DD,
                                   E_, n, (l == 3) ? 1 : 0);
    }

    k_head<<<(G + 255)/256, 256>>>(out, bout, G);
    k_pool<<<(n + 7)/8, 256>>>(Wout, bid, out, n);
}

// round 16
// speedup vs baseline: 1.0226x; 1.0052x over previous
#include <cuda_runtime.h>
#include <cuda_bf16.h>
#include <cstdint>

#define NMAX 200000
#define EMAX 400000
#define DD 128
#define HH 4
#define GDIM 148

typedef unsigned int uint;

// ---------------- scratch (device globals; no allocation) ----------------
__device__ __align__(16) float g_h[NMAX*DD];      // final-layer h (for pool)
__device__ __align__(16) uint  g_hh[NMAX*64];     // h hi-plane bf16 pairs
__device__ __align__(16) uint  g_hl[NMAX*64];     // h lo-plane bf16 pairs
__device__ __align__(16) float g_xl[NMAX*DD];
__device__ __align__(16) float g_xr[NMAX*DD];
__device__ __align__(16) float g_efull[(EMAX+NMAX)*HH];
__device__ __align__(16) float g_sums[NMAX*HH];
__device__ int g_deg[NMAX];
__device__ int g_off[NMAX];
__device__ int g_cur[NMAX];
__device__ int g_eid[EMAX+NMAX];
__device__ int g_total;

__device__ __forceinline__ void red4(float* p, float a, float b, float c, float d){
    asm volatile("red.global.add.v4.f32 [%0], {%1,%2,%3,%4};"
                 :: "l"(p), "f"(a), "f"(b), "f"(c), "f"(d) : "memory");
}

// split a pair of floats into bf16x2 (hi) + bf16x2 (lo residual)
__device__ __forceinline__ uint2 split2(float x0, float x1){
    __nv_bfloat162 h = __floats2bfloat162_rn(x0, x1);
    float r0 = x0 - __bfloat162float(h.x);
    float r1 = x1 - __bfloat162float(h.y);
    __nv_bfloat162 l = __floats2bfloat162_rn(r0, r1);
    uint2 u;
    u.x = *reinterpret_cast<uint32_t*>(&h);
    u.y = *reinterpret_cast<uint32_t*>(&l);
    return u;
}

// ---------------- atom encoder + split-plane store ----------------
__global__ void k_atom(const float* __restrict__ tab, const int* __restrict__ x, int n){
    int i = blockIdx.x;
    int d = threadIdx.x;        // 128 threads
    __shared__ int xf[9];
    if (d < 9) xf[d] = x[i*9 + d];
    __syncthreads();
    float s = 0.f;
#pragma unroll
    for (int f = 0; f < 9; ++f)
        s += tab[(f*16 + xf[f])*DD + d];
    float s1 = __shfl_down_sync(0xffffffffu, s, 1);
    if ((d & 1) == 0){
        uint2 u = split2(s, s1);
        g_hh[(size_t)i*64 + (d >> 1)] = u.x;
        g_hl[(size_t)i*64 + (d >> 1)] = u.y;
    }
}

__global__ void k_zero(int n){
    int i = blockIdx.x*blockDim.x + threadIdx.x;
    if (i == 0) g_total = 0;
    if (i >= n) return;
    g_deg[i] = 0;
    *(float4*)(g_sums + i*4) = make_float4(0.f,0.f,0.f,0.f);
}

__global__ void k_edge(const float* __restrict__ bond, const int* __restrict__ ei,
                       const int* __restrict__ ea, int E_){
    int e = blockIdx.x*blockDim.x + threadIdx.x;
    if (e >= E_) return;
    int tt  = ea[e];
    int dst = ei[E_ + e];
    float4 b = *(const float4*)(bond + tt*4);
    *(float4*)(g_efull + e*4) = b;
    red4(g_sums + dst*4, b.x, b.y, b.z, b.w);
    atomicAdd(g_deg + dst, 1);
}

// self-loop mean + atomic CSR offset assignment (order-free segments)
__global__ void k_self(int E_, int n){
    int i = blockIdx.x*blockDim.x + threadIdx.x;
    if (i >= n) return;
    int deg = g_deg[i];
    float inv = 1.0f / fmaxf((float)deg, 1.0f);
    float4 s = *(const float4*)(g_sums + i*4);
    *(float4*)(g_efull + (E_ + i)*4) = make_float4(s.x*inv, s.y*inv, s.z*inv, s.w*inv);
    int pos = atomicAdd(&g_total, deg + 1);
    g_off[i] = pos;
    g_cur[i] = pos;
}

__global__ void k_scatter(const int* __restrict__ ei, int E_, int n){
    int e = blockIdx.x*blockDim.x + threadIdx.x;
    if (e >= E_ + n) return;
    int dst = (e < E_) ? ei[E_ + e] : (e - E_);
    int pos = atomicAdd(g_cur + dst, 1);
    g_eid[pos] = e;
}

// ---------------- bf16-split dual GEMM via ldmatrix (R9 exact) ----------------
#define RSU 68   // uints per row (272 B)
#define MMA1(acc, a0,a1,a2,a3, b0,b1) \
    asm volatile("mma.sync.aligned.m16n8k16.row.col.f32.bf16.bf16.f32 " \
        "{%0,%1,%2,%3}, {%4,%5,%6,%7}, {%8,%9}, {%0,%1,%2,%3};" \
        : "+f"(acc[0]), "+f"(acc[1]), "+f"(acc[2]), "+f"(acc[3]) \
        : "r"(a0), "r"(a1), "r"(a2), "r"(a3), "r"(b0), "r"(b1))
#define LDSM4(f, addr) \
    asm volatile("ldmatrix.sync.aligned.m8n8.x4.shared.b16 {%0,%1,%2,%3}, [%4];" \
        : "=r"(f[0]), "=r"(f[1]), "=r"(f[2]), "=r"(f[3]) : "r"(addr))

__global__ __launch_bounds__(256, 1)
void k_tc(const float* __restrict__ Wl, const float* __restrict__ bl,
          const float* __restrict__ Wr, const float* __restrict__ br, int n){
    extern __shared__ uint smu[];
    uint* sBh = smu;                   // [256][RSU]
    uint* sBl = sBh + 256*RSU;
    uint* sAh = sBl + 256*RSU;         // [64][RSU]
    uint* sAl = sAh + 64*RSU;
    float* sBias = (float*)(sAl + 64*RSU);   // [256]
    int tid = threadIdx.x, wid = tid >> 5, lane = tid & 31;
    int gq = lane >> 2, tg = lane & 3;
    int wm = wid & 1, wn = wid >> 1;

    for (int idx = tid; idx < 256*64; idx += 256){
        int c = idx & 255, kp = idx >> 8;
        int k = kp*2;
        float w0, w1;
        if (c < 128){ w0 = Wl[k*DD + c];        w1 = Wl[(k+1)*DD + c]; }
        else        { w0 = Wr[k*DD + (c-128)];  w1 = Wr[(k+1)*DD + (c-128)]; }
        uint2 u = split2(w0, w1);
        sBh[c*RSU + kp] = u.x;
        sBl[c*RSU + kp] = u.y;
    }
    sBias[tid] = (tid < 128) ? bl[tid] : br[tid - 128];

    uint32_t sA_h32, sA_l32, sB_h32, sB_l32;
    asm("{ .reg .u64 t; cvta.to.shared.u64 t, %1; cvt.u32.u64 %0, t; }" : "=r"(sA_h32) : "l"(sAh));
    asm("{ .reg .u64 t; cvta.to.shared.u64 t, %1; cvt.u32.u64 %0, t; }" : "=r"(sA_l32) : "l"(sAl));
    asm("{ .reg .u64 t; cvta.to.shared.u64 t, %1; cvt.u32.u64 %0, t; }" : "=r"(sB_h32) : "l"(sBh));
    asm("{ .reg .u64 t; cvta.to.shared.u64 t, %1; cvt.u32.u64 %0, t; }" : "=r"(sB_l32) : "l"(sBl));

    int tiles = (n + 63) >> 6;
    uint4 preH[4], preL[4];
    {
        int base = blockIdx.x * 64;
#pragma unroll
        for (int r = 0; r < 4; ++r){
            int cidx = r*256 + tid;
            int node = cidx >> 4, ch = cidx & 15;
            int gn = base + node;
            if (gn < n){
                preH[r] = ((const uint4*)(g_hh + (size_t)gn*64))[ch];
                preL[r] = ((const uint4*)(g_hl + (size_t)gn*64))[ch];
            } else {
                preH[r] = make_uint4(0u,0u,0u,0u);
                preL[r] = make_uint4(0u,0u,0u,0u);
            }
        }
    }

    for (int tile = blockIdx.x; tile < tiles; tile += GDIM){
        __syncthreads();
#pragma unroll
        for (int r = 0; r < 4; ++r){
            int cidx = r*256 + tid;
            int node = cidx >> 4, ch = cidx & 15;
            *(uint4*)(sAh + node*RSU + ch*4) = preH[r];
            *(uint4*)(sAl + node*RSU + ch*4) = preL[r];
        }
        __syncthreads();
        if (tile + GDIM < tiles){
            int base = (tile + GDIM) * 64;
#pragma unroll
            for (int r = 0; r < 4; ++r){
                int cidx = r*256 + tid;
                int node = cidx >> 4, ch = cidx & 15;
                int gn = base + node;
                if (gn < n){
                    preH[r] = ((const uint4*)(g_hh + (size_t)gn*64))[ch];
                    preL[r] = ((const uint4*)(g_hl + (size_t)gn*64))[ch];
                } else {
                    preH[r] = make_uint4(0u,0u,0u,0u);
                    preL[r] = make_uint4(0u,0u,0u,0u);
                }
            }
        }

        float acc[2][8][4];
#pragma unroll
        for (int mb = 0; mb < 2; ++mb)
#pragma unroll
            for (int nb = 0; nb < 8; ++nb)
#pragma unroll
                for (int j = 0; j < 4; ++j) acc[mb][nb][j] = 0.f;

        uint32_t l15 = (uint32_t)(lane & 15);
        uint32_t lhi = (uint32_t)(lane >> 4) * 16u;

#pragma unroll 1
        for (int kc = 0; kc < 8; ++kc){
            uint32_t koff = (uint32_t)kc*32u + lhi;
            uint32_t ah[2][4], al[2][4], bh[4][4], blo[4][4];
#pragma unroll
            for (int mb = 0; mb < 2; ++mb){
                uint32_t ro = (uint32_t)(wm*32 + mb*16) + l15;
                LDSM4(ah[mb], sA_h32 + ro*272u + koff);
                LDSM4(al[mb], sA_l32 + ro*272u + koff);
            }
#pragma unroll
            for (int cb = 0; cb < 4; ++cb){
                uint32_t co = (uint32_t)(wn*64 + cb*16) + l15;
                LDSM4(bh[cb],  sB_h32 + co*272u + koff);
                LDSM4(blo[cb], sB_l32 + co*272u + koff);
            }
#pragma unroll
            for (int nb = 0; nb < 8; ++nb){
                int cb = nb >> 1, hf = nb & 1;
                uint32_t bh0 = bh[cb][hf],  bh1 = bh[cb][hf+2];
                uint32_t bl0 = blo[cb][hf], bl1 = blo[cb][hf+2];
#pragma unroll
                for (int mb = 0; mb < 2; ++mb){
                    MMA1(acc[mb][nb], ah[mb][0],ah[mb][1],ah[mb][2],ah[mb][3], bh0,bh1);
                    MMA1(acc[mb][nb], ah[mb][0],ah[mb][1],ah[mb][2],ah[mb][3], bl0,bl1);
                    MMA1(acc[mb][nb], al[mb][0],al[mb][1],al[mb][2],al[mb][3], bh0,bh1);
                }
            }
        }

        int base = tile*64;
#pragma unroll
        for (int mb = 0; mb < 2; ++mb){
            int gm0 = base + wm*32 + mb*16 + gq;
            int gm1 = gm0 + 8;
#pragma unroll
            for (int nb = 0; nb < 8; ++nb){
                int c0 = wn*64 + nb*8 + tg*2;
                float bx = sBias[c0], by = sBias[c0 + 1];
                float* outp = (c0 < 128) ? g_xl : g_xr;
                int cl = (c0 < 128) ? c0 : c0 - 128;
                if (gm0 < n)
                    *(float2*)(outp + (size_t)gm0*DD + cl)
                        = make_float2(acc[mb][nb][0] + bx, acc[mb][nb][1] + by);
                if (gm1 < n)
                    *(float2*)(outp + (size_t)gm1*DD + cl)
                        = make_float2(acc[mb][nb][2] + bx, acc[mb][nb][3] + by);
            }
        }
    }
}

// ---------------- CSR fused edge pass (R9 exact; off1 from deg) ----------------
__global__ void k_att2(const int* __restrict__ ei, const float* __restrict__ We,
                       const float* __restrict__ att, const float* __restrict__ cb,
                       int E_, int n, int last){
    __shared__ float sWe[4*DD];
    __shared__ float sAtt[DD];
    __shared__ float sCb[DD];
    int t = threadIdx.x;
    for (int i = t; i < 4*DD; i += 256) sWe[i] = We[i];
    if (t < DD){ sAtt[t] = att[t]; sCb[t] = cb[t]; }
    __syncthreads();

    int d = blockIdx.x*8 + (t >> 5);
    if (d >= n) return;
    int lane = t & 31;
    int off0 = g_off[d];
    int off1 = off0 + g_deg[d] + 1;
    int c0 = lane*4;

    float4 b4 = *(const float4*)(g_xr + (size_t)d*DD + c0);
    float acc0 = 0.f, acc1 = 0.f, acc2 = 0.f, acc3 = 0.f;
    float zacc = 0.f;

    for (int jb = off0; jb < off1; jb += 32){
        int m = min(32, off1 - jb);
        int idx = 0, src = d;
        if (lane < m){
            idx = g_eid[jb + lane];
            src = (idx < E_) ? ei[idx] : d;
        }
#pragma unroll 1
        for (int jj = 0; jj < m; ++jj){
            int eidx = __shfl_sync(0xffffffffu, idx, jj);
            int esrc = __shfl_sync(0xffffffffu, src, jj);
            float4 e4 = *(const float4*)(g_efull + (size_t)eidx*4);
            float4 a4 = *(const float4*)(g_xl + (size_t)esrc*DD + c0);
            float av[4] = {a4.x, a4.y, a4.z, a4.w};
            float bv[4] = {b4.x, b4.y, b4.z, b4.w};
            float p = 0.f;
#pragma unroll
            for (int j = 0; j < 4; ++j){
                int c = c0 + j;
                float ee = e4.x*sWe[c] + e4.y*sWe[DD + c]
                         + e4.z*sWe[2*DD + c] + e4.w*sWe[3*DD + c];
                float g = av[j] + bv[j] + ee;
                g = (g > 0.f) ? g : 0.2f*g;
                p += g * sAtt[c];
            }
            p += __shfl_xor_sync(0xffffffffu, p, 1);
            p += __shfl_xor_sync(0xffffffffu, p, 2);
            p += __shfl_xor_sync(0xffffffffu, p, 4);
            float w = 0.f;
            if ((lane & 7) == 0){
                w = expf(p);
                zacc += w;
            }
            w = __shfl_sync(0xffffffffu, w, lane & 24);
            acc0 += av[0]*w; acc1 += av[1]*w; acc2 += av[2]*w; acc3 += av[3]*w;
        }
    }

    float z = __shfl_sync(0xffffffffu, zacc, lane & 24);
    float inv = 1.0f / (z + 1e-16f);
    float4 o;
    o.x = acc0*inv + sCb[c0];
    o.y = acc1*inv + sCb[c0+1];
    o.z = acc2*inv + sCb[c0+2];
    o.w = acc3*inv + sCb[c0+3];

    if (last){
        *(float4*)(g_h + (size_t)d*DD + c0) = o;
        return;
    }
    o.x = fmaxf(o.x, 0.f); o.y = fmaxf(o.y, 0.f);
    o.z = fmaxf(o.z, 0.f); o.w = fmaxf(o.w, 0.f);
    uint2 u0 = split2(o.x, o.y);
    uint2 u1 = split2(o.z, o.w);
    *(uint2*)(g_hh + (size_t)d*64 + lane*2) = make_uint2(u0.x, u1.x);
    *(uint2*)(g_hl + (size_t)d*64 + lane*2) = make_uint2(u0.y, u1.y);
}

// ---------------- head ----------------
__global__ void k_head(float* out, const float* __restrict__ bout, int G){
    int g = blockIdx.x*blockDim.x + threadIdx.x;
    if (g < G) out[g] = bout[0];
}

__global__ void k_pool(const float* __restrict__ Wout, const int* __restrict__ bid,
                       float* out, int n){
    int gw   = blockIdx.x*8 + (threadIdx.x >> 5);
    int lane = threadIdx.x & 31;
    if (gw >= n) return;
    float4 hv = *(const float4*)(g_h + (size_t)gw*DD + lane*4);
    float4 wv = *(const float4*)(Wout + lane*4);
    float p = hv.x*wv.x + hv.y*wv.y + hv.z*wv.z + hv.w*wv.w;
#pragma unroll
    for (int o = 16; o > 0; o >>= 1) p += __shfl_xor_sync(0xffffffffu, p, o);
    if (lane == 0) atomicAdd(out + bid[gw], p);
}

// ---------------- launch ----------------
extern "C" void kernel_launch(void* const* d_in, const int* in_sizes, int n_in,
                              void* d_out, int out_size){
    const float* atab = (const float*)d_in[0];
    const float* bond = (const float*)d_in[1];
    const float* Wl   = (const float*)d_in[2];
    const float* bl   = (const float*)d_in[3];
    const float* Wr   = (const float*)d_in[4];
    const float* br   = (const float*)d_in[5];
    const float* We   = (const float*)d_in[6];
    const float* att  = (const float*)d_in[7];
    const float* cb   = (const float*)d_in[8];
    const float* Wout = (const float*)d_in[9];
    const float* bout = (const float*)d_in[10];
    const int*   x    = (const int*)d_in[11];
    const int*   ei   = (const int*)d_in[12];
    const int*   ea   = (const int*)d_in[13];
    const int*   bid  = (const int*)d_in[14];

    int n  = in_sizes[11] / 9;
    int E_ = in_sizes[13];
    int G  = out_size;
    float* out = (float*)d_out;

    const int SMEM = (256*RSU*2 + 64*RSU*2)*4 + 256*4;   // ~171 KB

    static int init_done = 0;
    static cudaStream_t s2;
    static cudaEvent_t evFork, evJoin;
    if (!init_done){
        cudaFuncSetAttribute(k_tc, cudaFuncAttributeMaxDynamicSharedMemorySize, SMEM);
        cudaStreamCreateWithFlags(&s2, cudaStreamNonBlocking);
        cudaEventCreateWithFlags(&evFork, cudaEventDisableTiming);
        cudaEventCreateWithFlags(&evJoin, cudaEventDisableTiming);
        init_done = 1;
    }

    int nb = (n + 255)/256;
    int M  = E_ + n;

    // fork: side stream builds CSR + e_full + head init while main runs
    // atom encoder + layer-0 GEMM (independent work).
    cudaEventRecord(evFork, 0);
    cudaStreamWaitEvent(s2, evFork, 0);

    // side chain (feeds k_att2 layer 0 only)
    k_zero<<<nb, 256, 0, s2>>>(n);
    k_edge<<<(E_ + 255)/256, 256, 0, s2>>>(bond, ei, ea, E_);
    k_self<<<nb, 256, 0, s2>>>(E_, n);
    k_scatter<<<(M + 255)/256, 256, 0, s2>>>(ei, E_, n);
    k_head<<<(G + 255)/256, 256, 0, s2>>>(out, bout, G);
    cudaEventRecord(evJoin, s2);

    // main chain
    k_atom<<<n, 128>>>(atab, x, n);
    k_tc<<<GDIM, 256, SMEM>>>(Wl, bl, Wr, br, n);

    cudaStreamWaitEvent(0, evJoin, 0);
    k_att2<<<(n + 7)/8, 256>>>(ei, We, att, cb, E_, n, 0);

    for (int l = 1; l < 4; ++l){
        k_tc<<<GDIM, 256, SMEM>>>(Wl + l*DD*DD, bl + l*DD, Wr + l*DD*DD, br + l*DD, n);
        k_att2<<<(n + 7)/8, 256>>>(ei, We + l*4*DD, att + l*DD, cb + l*DD,
                                   E_, n, (l == 3) ? 1 : 0);
    }

    k_pool<<<(n + 7)/8, 256>>>(Wout, bid, out, n);
}

// round 17
// speedup vs baseline: 1.0403x; 1.0173x over previous
#include <cuda_runtime.h>
#include <cuda_bf16.h>
#include <cstdint>

#define NMAX 200000
#define EMAX 400000
#define DD 128
#define HH 4
#define GDIM 148

typedef unsigned int uint;

// ---------------- scratch (device globals; no allocation) ----------------
__device__ __align__(16) uint  g_hh[NMAX*64];     // h hi-plane bf16 pairs
__device__ __align__(16) uint  g_hl[NMAX*64];     // h lo-plane bf16 pairs
__device__ __align__(16) float g_xl[NMAX*DD];
__device__ __align__(16) float g_xr[NMAX*DD];
__device__ __align__(16) float g_efull[(EMAX+NMAX)*HH];
__device__ __align__(16) float g_sums[NMAX*HH];
__device__ int g_deg[NMAX];
__device__ int g_off[NMAX];
__device__ int g_cur[NMAX];
__device__ int g_eid[EMAX+NMAX];
__device__ int g_total;

__device__ __forceinline__ void red4(float* p, float a, float b, float c, float d){
    asm volatile("red.global.add.v4.f32 [%0], {%1,%2,%3,%4};"
                 :: "l"(p), "f"(a), "f"(b), "f"(c), "f"(d) : "memory");
}

// split a pair of floats into bf16x2 (hi) + bf16x2 (lo residual)
__device__ __forceinline__ uint2 split2(float x0, float x1){
    __nv_bfloat162 h = __floats2bfloat162_rn(x0, x1);
    float r0 = x0 - __bfloat162float(h.x);
    float r1 = x1 - __bfloat162float(h.y);
    __nv_bfloat162 l = __floats2bfloat162_rn(r0, r1);
    uint2 u;
    u.x = *reinterpret_cast<uint32_t*>(&h);
    u.y = *reinterpret_cast<uint32_t*>(&l);
    return u;
}

// ---------------- atom encoder + split-plane store ----------------
__global__ void k_atom(const float* __restrict__ tab, const int* __restrict__ x, int n){
    int i = blockIdx.x;
    int d = threadIdx.x;        // 128 threads
    __shared__ int xf[9];
    if (d < 9) xf[d] = x[i*9 + d];
    __syncthreads();
    float s = 0.f;
#pragma unroll
    for (int f = 0; f < 9; ++f)
        s += tab[(f*16 + xf[f])*DD + d];
    float s1 = __shfl_down_sync(0xffffffffu, s, 1);
    if ((d & 1) == 0){
        uint2 u = split2(s, s1);
        g_hh[(size_t)i*64 + (d >> 1)] = u.x;
        g_hl[(size_t)i*64 + (d >> 1)] = u.y;
    }
}

__global__ void k_zero(int n){
    int i = blockIdx.x*blockDim.x + threadIdx.x;
    if (i == 0) g_total = 0;
    if (i >= n) return;
    g_deg[i] = 0;
    *(float4*)(g_sums + i*4) = make_float4(0.f,0.f,0.f,0.f);
}

__global__ void k_edge(const float* __restrict__ bond, const int* __restrict__ ei,
                       const int* __restrict__ ea, int E_){
    int e = blockIdx.x*blockDim.x + threadIdx.x;
    if (e >= E_) return;
    int tt  = ea[e];
    int dst = ei[E_ + e];
    float4 b = *(const float4*)(bond + tt*4);
    *(float4*)(g_efull + e*4) = b;
    red4(g_sums + dst*4, b.x, b.y, b.z, b.w);
    atomicAdd(g_deg + dst, 1);
}

// self-loop mean + atomic CSR offset assignment (order-free segments)
__global__ void k_self(int E_, int n){
    int i = blockIdx.x*blockDim.x + threadIdx.x;
    if (i >= n) return;
    int deg = g_deg[i];
    float inv = 1.0f / fmaxf((float)deg, 1.0f);
    float4 s = *(const float4*)(g_sums + i*4);
    *(float4*)(g_efull + (E_ + i)*4) = make_float4(s.x*inv, s.y*inv, s.z*inv, s.w*inv);
    int pos = atomicAdd(&g_total, deg + 1);
    g_off[i] = pos;
    g_cur[i] = pos;
}

__global__ void k_scatter(const int* __restrict__ ei, int E_, int n){
    int e = blockIdx.x*blockDim.x + threadIdx.x;
    if (e >= E_ + n) return;
    int dst = (e < E_) ? ei[E_ + e] : (e - E_);
    int pos = atomicAdd(g_cur + dst, 1);
    g_eid[pos] = e;
}

// ---------------- bf16-split dual GEMM via ldmatrix (R9 exact) ----------------
#define RSU 68   // uints per row (272 B)
#define MMA1(acc, a0,a1,a2,a3, b0,b1) \
    asm volatile("mma.sync.aligned.m16n8k16.row.col.f32.bf16.bf16.f32 " \
        "{%0,%1,%2,%3}, {%4,%5,%6,%7}, {%8,%9}, {%0,%1,%2,%3};" \
        : "+f"(acc[0]), "+f"(acc[1]), "+f"(acc[2]), "+f"(acc[3]) \
        : "r"(a0), "r"(a1), "r"(a2), "r"(a3), "r"(b0), "r"(b1))
#define LDSM4(f, addr) \
    asm volatile("ldmatrix.sync.aligned.m8n8.x4.shared.b16 {%0,%1,%2,%3}, [%4];" \
        : "=r"(f[0]), "=r"(f[1]), "=r"(f[2]), "=r"(f[3]) : "r"(addr))

__global__ __launch_bounds__(256, 1)
void k_tc(const float* __restrict__ Wl, const float* __restrict__ bl,
          const float* __restrict__ Wr, const float* __restrict__ br, int n){
    extern __shared__ uint smu[];
    uint* sBh = smu;                   // [256][RSU]
    uint* sBl = sBh + 256*RSU;
    uint* sAh = sBl + 256*RSU;         // [64][RSU]
    uint* sAl = sAh + 64*RSU;
    float* sBias = (float*)(sAl + 64*RSU);   // [256]
    int tid = threadIdx.x, wid = tid >> 5, lane = tid & 31;
    int gq = lane >> 2, tg = lane & 3;
    int wm = wid & 1, wn = wid >> 1;

    for (int idx = tid; idx < 256*64; idx += 256){
        int c = idx & 255, kp = idx >> 8;
        int k = kp*2;
        float w0, w1;
        if (c < 128){ w0 = Wl[k*DD + c];        w1 = Wl[(k+1)*DD + c]; }
        else        { w0 = Wr[k*DD + (c-128)];  w1 = Wr[(k+1)*DD + (c-128)]; }
        uint2 u = split2(w0, w1);
        sBh[c*RSU + kp] = u.x;
        sBl[c*RSU + kp] = u.y;
    }
    sBias[tid] = (tid < 128) ? bl[tid] : br[tid - 128];

    uint32_t sA_h32, sA_l32, sB_h32, sB_l32;
    asm("{ .reg .u64 t; cvta.to.shared.u64 t, %1; cvt.u32.u64 %0, t; }" : "=r"(sA_h32) : "l"(sAh));
    asm("{ .reg .u64 t; cvta.to.shared.u64 t, %1; cvt.u32.u64 %0, t; }" : "=r"(sA_l32) : "l"(sAl));
    asm("{ .reg .u64 t; cvta.to.shared.u64 t, %1; cvt.u32.u64 %0, t; }" : "=r"(sB_h32) : "l"(sBh));
    asm("{ .reg .u64 t; cvta.to.shared.u64 t, %1; cvt.u32.u64 %0, t; }" : "=r"(sB_l32) : "l"(sBl));

    int tiles = (n + 63) >> 6;
    uint4 preH[4], preL[4];
    {
        int base = blockIdx.x * 64;
#pragma unroll
        for (int r = 0; r < 4; ++r){
            int cidx = r*256 + tid;
            int node = cidx >> 4, ch = cidx & 15;
            int gn = base + node;
            if (gn < n){
                preH[r] = ((const uint4*)(g_hh + (size_t)gn*64))[ch];
                preL[r] = ((const uint4*)(g_hl + (size_t)gn*64))[ch];
            } else {
                preH[r] = make_uint4(0u,0u,0u,0u);
                preL[r] = make_uint4(0u,0u,0u,0u);
            }
        }
    }

    for (int tile = blockIdx.x; tile < tiles; tile += GDIM){
        __syncthreads();
#pragma unroll
        for (int r = 0; r < 4; ++r){
            int cidx = r*256 + tid;
            int node = cidx >> 4, ch = cidx & 15;
            *(uint4*)(sAh + node*RSU + ch*4) = preH[r];
            *(uint4*)(sAl + node*RSU + ch*4) = preL[r];
        }
        __syncthreads();
        if (tile + GDIM < tiles){
            int base = (tile + GDIM) * 64;
#pragma unroll
            for (int r = 0; r < 4; ++r){
                int cidx = r*256 + tid;
                int node = cidx >> 4, ch = cidx & 15;
                int gn = base + node;
                if (gn < n){
                    preH[r] = ((const uint4*)(g_hh + (size_t)gn*64))[ch];
                    preL[r] = ((const uint4*)(g_hl + (size_t)gn*64))[ch];
                } else {
                    preH[r] = make_uint4(0u,0u,0u,0u);
                    preL[r] = make_uint4(0u,0u,0u,0u);
                }
            }
        }

        float acc[2][8][4];
#pragma unroll
        for (int mb = 0; mb < 2; ++mb)
#pragma unroll
            for (int nb = 0; nb < 8; ++nb)
#pragma unroll
                for (int j = 0; j < 4; ++j) acc[mb][nb][j] = 0.f;

        uint32_t l15 = (uint32_t)(lane & 15);
        uint32_t lhi = (uint32_t)(lane >> 4) * 16u;

#pragma unroll 1
        for (int kc = 0; kc < 8; ++kc){
            uint32_t koff = (uint32_t)kc*32u + lhi;
            uint32_t ah[2][4], al[2][4], bh[4][4], blo[4][4];
#pragma unroll
            for (int mb = 0; mb < 2; ++mb){
                uint32_t ro = (uint32_t)(wm*32 + mb*16) + l15;
                LDSM4(ah[mb], sA_h32 + ro*272u + koff);
                LDSM4(al[mb], sA_l32 + ro*272u + koff);
            }
#pragma unroll
            for (int cb = 0; cb < 4; ++cb){
                uint32_t co = (uint32_t)(wn*64 + cb*16) + l15;
                LDSM4(bh[cb],  sB_h32 + co*272u + koff);
                LDSM4(blo[cb], sB_l32 + co*272u + koff);
            }
#pragma unroll
            for (int nb = 0; nb < 8; ++nb){
                int cb = nb >> 1, hf = nb & 1;
                uint32_t bh0 = bh[cb][hf],  bh1 = bh[cb][hf+2];
                uint32_t bl0 = blo[cb][hf], bl1 = blo[cb][hf+2];
#pragma unroll
                for (int mb = 0; mb < 2; ++mb){
                    MMA1(acc[mb][nb], ah[mb][0],ah[mb][1],ah[mb][2],ah[mb][3], bh0,bh1);
                    MMA1(acc[mb][nb], ah[mb][0],ah[mb][1],ah[mb][2],ah[mb][3], bl0,bl1);
                    MMA1(acc[mb][nb], al[mb][0],al[mb][1],al[mb][2],al[mb][3], bh0,bh1);
                }
            }
        }

        int base = tile*64;
#pragma unroll
        for (int mb = 0; mb < 2; ++mb){
            int gm0 = base + wm*32 + mb*16 + gq;
            int gm1 = gm0 + 8;
#pragma unroll
            for (int nb = 0; nb < 8; ++nb){
                int c0 = wn*64 + nb*8 + tg*2;
                float bx = sBias[c0], by = sBias[c0 + 1];
                float* outp = (c0 < 128) ? g_xl : g_xr;
                int cl = (c0 < 128) ? c0 : c0 - 128;
                if (gm0 < n)
                    *(float2*)(outp + (size_t)gm0*DD + cl)
                        = make_float2(acc[mb][nb][0] + bx, acc[mb][nb][1] + by);
                if (gm1 < n)
                    *(float2*)(outp + (size_t)gm1*DD + cl)
                        = make_float2(acc[mb][nb][2] + bx, acc[mb][nb][3] + by);
            }
        }
    }
}

// ---------------- CSR fused edge pass (R9 exact; fused head on last layer) ----------------
__global__ void k_att2(const int* __restrict__ ei, const float* __restrict__ We,
                       const float* __restrict__ att, const float* __restrict__ cb,
                       const float* __restrict__ Wout, const int* __restrict__ bid,
                       float* __restrict__ out, int E_, int n, int last){
    __shared__ float sWe[4*DD];
    __shared__ float sAtt[DD];
    __shared__ float sCb[DD];
    int t = threadIdx.x;
    for (int i = t; i < 4*DD; i += 256) sWe[i] = We[i];
    if (t < DD){ sAtt[t] = att[t]; sCb[t] = cb[t]; }
    __syncthreads();

    int d = blockIdx.x*8 + (t >> 5);
    if (d >= n) return;
    int lane = t & 31;
    int off0 = g_off[d];
    int off1 = off0 + g_deg[d] + 1;
    int c0 = lane*4;

    float4 b4 = *(const float4*)(g_xr + (size_t)d*DD + c0);
    float acc0 = 0.f, acc1 = 0.f, acc2 = 0.f, acc3 = 0.f;
    float zacc = 0.f;

    for (int jb = off0; jb < off1; jb += 32){
        int m = min(32, off1 - jb);
        int idx = 0, src = d;
        if (lane < m){
            idx = g_eid[jb + lane];
            src = (idx < E_) ? ei[idx] : d;
        }
#pragma unroll 1
        for (int jj = 0; jj < m; ++jj){
            int eidx = __shfl_sync(0xffffffffu, idx, jj);
            int esrc = __shfl_sync(0xffffffffu, src, jj);
            float4 e4 = *(const float4*)(g_efull + (size_t)eidx*4);
            float4 a4 = *(const float4*)(g_xl + (size_t)esrc*DD + c0);
            float av[4] = {a4.x, a4.y, a4.z, a4.w};
            float bv[4] = {b4.x, b4.y, b4.z, b4.w};
            float p = 0.f;
#pragma unroll
            for (int j = 0; j < 4; ++j){
                int c = c0 + j;
                float ee = e4.x*sWe[c] + e4.y*sWe[DD + c]
                         + e4.z*sWe[2*DD + c] + e4.w*sWe[3*DD + c];
                float g = av[j] + bv[j] + ee;
                g = (g > 0.f) ? g : 0.2f*g;
                p += g * sAtt[c];
            }
            p += __shfl_xor_sync(0xffffffffu, p, 1);
            p += __shfl_xor_sync(0xffffffffu, p, 2);
            p += __shfl_xor_sync(0xffffffffu, p, 4);
            float w = 0.f;
            if ((lane & 7) == 0){
                w = expf(p);
                zacc += w;
            }
            w = __shfl_sync(0xffffffffu, w, lane & 24);
            acc0 += av[0]*w; acc1 += av[1]*w; acc2 += av[2]*w; acc3 += av[3]*w;
        }
    }

    float z = __shfl_sync(0xffffffffu, zacc, lane & 24);
    float inv = 1.0f / (z + 1e-16f);
    float4 o;
    o.x = acc0*inv + sCb[c0];
    o.y = acc1*inv + sCb[c0+1];
    o.z = acc2*inv + sCb[c0+2];
    o.w = acc3*inv + sCb[c0+3];

    if (last){
        // fused head: out[bid[d]] += h[d] . Wout
        float4 wv = *(const float4*)(Wout + c0);
        float p = o.x*wv.x + o.y*wv.y + o.z*wv.z + o.w*wv.w;
#pragma unroll
        for (int off = 16; off > 0; off >>= 1)
            p += __shfl_xor_sync(0xffffffffu, p, off);
        if (lane == 0) atomicAdd(out + bid[d], p);
        return;
    }
    o.x = fmaxf(o.x, 0.f); o.y = fmaxf(o.y, 0.f);
    o.z = fmaxf(o.z, 0.f); o.w = fmaxf(o.w, 0.f);
    uint2 u0 = split2(o.x, o.y);
    uint2 u1 = split2(o.z, o.w);
    *(uint2*)(g_hh + (size_t)d*64 + lane*2) = make_uint2(u0.x, u1.x);
    *(uint2*)(g_hl + (size_t)d*64 + lane*2) = make_uint2(u0.y, u1.y);
}

// ---------------- head init ----------------
__global__ void k_head(float* out, const float* __restrict__ bout, int G){
    int g = blockIdx.x*blockDim.x + threadIdx.x;
    if (g < G) out[g] = bout[0];
}

// ---------------- launch ----------------
extern "C" void kernel_launch(void* const* d_in, const int* in_sizes, int n_in,
                              void* d_out, int out_size){
    const float* atab = (const float*)d_in[0];
    const float* bond = (const float*)d_in[1];
    const float* Wl   = (const float*)d_in[2];
    const float* bl   = (const float*)d_in[3];
    const float* Wr   = (const float*)d_in[4];
    const float* br   = (const float*)d_in[5];
    const float* We   = (const float*)d_in[6];
    const float* att  = (const float*)d_in[7];
    const float* cb   = (const float*)d_in[8];
    const float* Wout = (const float*)d_in[9];
    const float* bout = (const float*)d_in[10];
    const int*   x    = (const int*)d_in[11];
    const int*   ei   = (const int*)d_in[12];
    const int*   ea   = (const int*)d_in[13];
    const int*   bid  = (const int*)d_in[14];

    int n  = in_sizes[11] / 9;
    int E_ = in_sizes[13];
    int G  = out_size;
    float* out = (float*)d_out;

    const int SMEM = (256*RSU*2 + 64*RSU*2)*4 + 256*4;   // ~171 KB

    static int init_done = 0;
    static cudaStream_t s2;
    static cudaEvent_t evFork, evJoin;
    if (!init_done){
        cudaFuncSetAttribute(k_tc, cudaFuncAttributeMaxDynamicSharedMemorySize, SMEM);
        cudaStreamCreateWithFlags(&s2, cudaStreamNonBlocking);
        cudaEventCreateWithFlags(&evFork, cudaEventDisableTiming);
        cudaEventCreateWithFlags(&evJoin, cudaEventDisableTiming);
        init_done = 1;
    }

    int nb = (n + 255)/256;
    int M  = E_ + n;

    // fork: side stream builds CSR + e_full + head init while main runs
    // atom encoder + layer-0 GEMM (independent work).
    cudaEventRecord(evFork, 0);
    cudaStreamWaitEvent(s2, evFork, 0);

    // side chain (feeds k_att2 layer 0 only)
    k_zero<<<nb, 256, 0, s2>>>(n);
    k_edge<<<(E_ + 255)/256, 256, 0, s2>>>(bond, ei, ea, E_);
    k_self<<<nb, 256, 0, s2>>>(E_, n);
    k_scatter<<<(M + 255)/256, 256, 0, s2>>>(ei, E_, n);
    k_head<<<(G + 255)/256, 256, 0, s2>>>(out, bout, G);
    cudaEventRecord(evJoin, s2);

    // main chain
    k_atom<<<n, 128>>>(atab, x, n);
    k_tc<<<GDIM, 256, SMEM>>>(Wl, bl, Wr, br, n);

    cudaStreamWaitEvent(0, evJoin, 0);
    k_att2<<<(n + 7)/8, 256>>>(ei, We, att, cb, Wout, bid, out, E_, n, 0);

    for (int l = 1; l < 4; ++l){
        k_tc<<<GDIM, 256, SMEM>>>(Wl + l*DD*DD, bl + l*DD, Wr + l*DD*DD, br + l*DD, n);
        k_att2<<<(n + 7)/8, 256>>>(ei, We + l*4*DD, att + l*DD, cb + l*DD,
                                   Wout, bid, out, E_, n, (l == 3) ? 1 : 0);
    }
}